// round 4
// baseline (speedup 1.0000x reference)
#include <cuda_runtime.h>

// TritonDualLIF: x [T=16,B=32,N=196,C=512] f32, decay scalar.
// v = d*v + x[t]; vpool[t,b,c] = mean_n(pre-reset v); s = (v>=1); v = s?0:v.
// out = spikes [T,B,N,C] ++ vpool [T,B,C].
//
// N split into 4 chunks (gridDim.z) for occupancy; last-arriving CTA of each
// (b,cblk) group combines the 4 chunk partials and writes vpool.

#define T_ 16
#define B_ 32
#define N_ 196
#define C_ 512
#define NH 4
#define NSUB 49            // 196/4
#define NLANES 8
#define JMAX 7             // ty==0 -> 7 iters, else 6  (7 + 7*6 = 49)
#define NGROUP 512         // B_ * (C_/32)

// Per-chunk partial sums: [NH][group][T*32] = 4 MB.
__device__ float    g_part[NH * NGROUP * T_ * 32];
// Arrival counters per group; parity mod 4 is what matters (graph-replay safe).
__device__ unsigned g_ctr[NGROUP];

__global__ __launch_bounds__(256, 7)
void lif_dual_kernel(const float* __restrict__ x,
                     const float* __restrict__ decay,
                     float* __restrict__ out) {
    const int tx   = threadIdx.x;     // c lane 0..31
    const int ty   = threadIdx.y;     // n lane 0..7
    const int cblk = blockIdx.x;      // 0..15
    const int b    = blockIdx.y;      // 0..31
    const int z    = blockIdx.z;      // 0..3  (N chunk)
    const int c    = cblk * 32 + tx;
    const float d  = decay[0];

    float* __restrict__ spikes = out;
    float* __restrict__ vpool  = out + (size_t)T_ * B_ * N_ * C_;

    __shared__ float red[NLANES][T_][32];   // exclusive slots, no in-loop sync
    __shared__ int   s_last;

    float v[JMAX];
#pragma unroll
    for (int j = 0; j < JMAX; ++j) v[j] = 0.0f;

    const unsigned bbase   = (unsigned)b * (N_ * C_)
                           + (unsigned)(z * NSUB + ty) * C_ + (unsigned)c;
    const unsigned tstride = (unsigned)(B_ * N_ * C_);
    const int jcnt = (ty == 0) ? JMAX : (JMAX - 1);

    for (int t = 0; t < T_; ++t) {
        const unsigned tb = (unsigned)t * tstride + bbase;
        float partial = 0.0f;
#pragma unroll
        for (int j = 0; j < JMAX; ++j) {
            if (j < jcnt) {
                const unsigned idx = tb + (unsigned)(j * (NLANES * C_));
                const float xv = __ldcs(&x[idx]);
                const float vv = fmaf(d, v[j], xv);
                partial += vv;                        // pre-reset membrane
                const bool fire = (vv >= 1.0f);
                __stcs(&spikes[idx], fire ? 1.0f : 0.0f);
                v[j] = fire ? 0.0f : vv;              // hard reset
            }
        }
        red[ty][t][tx] = partial;                     // exclusive slot
    }

    __syncthreads();

    // Reduce 8 lanes -> chunk partial [T_*32] and store to scratch.
    const int tid   = ty * 32 + tx;
    const int group = b * 16 + cblk;                  // 0..511
    float* gp = &g_part[((unsigned)z * NGROUP + (unsigned)group) * (T_ * 32)];
#pragma unroll
    for (int o = 0; o < 2; ++o) {
        const int oi = tid + o * 256;                 // 0..511
        const int t  = oi >> 5;
        const int cc = oi & 31;
        float sum = 0.0f;
#pragma unroll
        for (int k = 0; k < NLANES; ++k) sum += red[k][t][cc];
        gp[oi] = sum;
    }

    // Publish, then elect the last-arriving CTA of this 4-chunk group.
    __threadfence();
    __syncthreads();
    if (tid == 0) {
        const unsigned old = atomicAdd(&g_ctr[group], 1u);
        s_last = ((old & 3u) == 3u) ? 1 : 0;
    }
    __syncthreads();

    if (s_last) {
        __threadfence();   // acquire: see all chunks' scratch writes
        const float* p0 = &g_part[((unsigned)0 * NGROUP + (unsigned)group) * (T_ * 32)];
        const float* p1 = &g_part[((unsigned)1 * NGROUP + (unsigned)group) * (T_ * 32)];
        const float* p2 = &g_part[((unsigned)2 * NGROUP + (unsigned)group) * (T_ * 32)];
        const float* p3 = &g_part[((unsigned)3 * NGROUP + (unsigned)group) * (T_ * 32)];
#pragma unroll
        for (int o = 0; o < 2; ++o) {
            const int oi = tid + o * 256;
            const int t  = oi >> 5;
            const int cc = oi & 31;
            const float sum = ((p0[oi] + p1[oi]) + (p2[oi] + p3[oi]));
            vpool[(unsigned)t * (B_ * C_) + (unsigned)b * C_
                  + (unsigned)(cblk * 32 + cc)] = sum * (1.0f / (float)N_);
        }
    }
}

extern "C" void kernel_launch(void* const* d_in, const int* in_sizes, int n_in,
                              void* d_out, int out_size) {
    const float* x     = (const float*)d_in[0];
    const float* decay = (const float*)d_in[1];
    float* out = (float*)d_out;

    dim3 block(32, NLANES);             // 256 threads
    dim3 grid(C_ / 32, B_, NH);         // 16 x 32 x 4 = 2048 blocks
    lif_dual_kernel<<<grid, block>>>(x, decay, out);
}

// round 5
// speedup vs baseline: 1.8174x; 1.8174x over previous
#include <cuda_runtime.h>

// TritonDualLIF: x [T=16,B=32,N=196,C=512] f32, decay scalar.
// v = d*v + x[t]; vpool[t,b,c] = mean_n(pre-reset v); s = (v>=1); v = s?0:v.
// out = spikes [T,B,N,C] ++ vpool [T,B,C].
//
// N split into 2 chunks of 98 (gridDim.z) for occupancy while keeping
// per-thread MLP ~12. Last-arriving CTA of each (b,cblk) pair combines the
// two chunk partials and writes vpool.

#define T_ 16
#define B_ 32
#define N_ 196
#define C_ 512
#define NH 2
#define NSUB 98            // 196/2
#define NLANES 8
#define JFULL 12           // uniform iterations: 8*12 = 96 rows
// rows 96,97 of each chunk handled by ty==0,1 as a 13th iteration
#define NGROUP 512         // B_ * (C_/32)

// Per-chunk partial sums: [NH][group][T*32] = 2 MB.
__device__ float    g_part[NH * NGROUP * T_ * 32];
__device__ unsigned g_ctr[NGROUP];   // parity mod 2 elects the combiner

__global__ __launch_bounds__(256, 4)
void lif_dual_kernel(const float* __restrict__ x,
                     const float* __restrict__ decay,
                     float* __restrict__ out) {
    const int tx   = threadIdx.x;     // c lane 0..31
    const int ty   = threadIdx.y;     // n lane 0..7
    const int cblk = blockIdx.x;      // 0..15
    const int b    = blockIdx.y;      // 0..31
    const int z    = blockIdx.z;      // 0..1  (N chunk)
    const int c    = cblk * 32 + tx;
    const float d  = decay[0];

    float* __restrict__ spikes = out;
    float* __restrict__ vpool  = out + (size_t)T_ * B_ * N_ * C_;

    __shared__ float red[NLANES][T_][32];   // exclusive slots, no in-loop sync
    __shared__ int   s_last;

    float v[JFULL + 1];
#pragma unroll
    for (int j = 0; j <= JFULL; ++j) v[j] = 0.0f;

    const unsigned bbase   = (unsigned)b * (N_ * C_)
                           + (unsigned)(z * NSUB + ty) * C_ + (unsigned)c;
    const unsigned tstride = (unsigned)(B_ * N_ * C_);
    const bool extra = (ty < 2);      // rows 96+ty of this chunk

    for (int t = 0; t < T_; ++t) {
        const unsigned tb = (unsigned)t * tstride + bbase;
        float partial = 0.0f;
#pragma unroll
        for (int j = 0; j < JFULL; ++j) {
            const unsigned idx = tb + (unsigned)(j * (NLANES * C_));
            const float xv = x[idx];
            const float vv = fmaf(d, v[j], xv);
            partial += vv;                        // pre-reset membrane
            const bool fire = (vv >= 1.0f);
            spikes[idx] = fire ? 1.0f : 0.0f;
            v[j] = fire ? 0.0f : vv;              // hard reset
        }
        if (extra) {
            const unsigned idx = tb + (unsigned)(JFULL * (NLANES * C_));
            const float xv = x[idx];
            const float vv = fmaf(d, v[JFULL], xv);
            partial += vv;
            const bool fire = (vv >= 1.0f);
            spikes[idx] = fire ? 1.0f : 0.0f;
            v[JFULL] = fire ? 0.0f : vv;
        }
        red[ty][t][tx] = partial;                 // exclusive slot
    }

    __syncthreads();

    // Reduce 8 lanes -> chunk partial [T_*32], store to scratch.
    const int tid   = ty * 32 + tx;
    const int group = b * 16 + cblk;              // 0..511
    float* gp = &g_part[((unsigned)z * NGROUP + (unsigned)group) * (T_ * 32)];
#pragma unroll
    for (int o = 0; o < 2; ++o) {
        const int oi = tid + o * 256;             // 0..511
        const int t  = oi >> 5;
        const int cc = oi & 31;
        float sum = 0.0f;
#pragma unroll
        for (int k = 0; k < NLANES; ++k) sum += red[k][t][cc];
        gp[oi] = sum;
    }

    __threadfence();
    __syncthreads();
    if (tid == 0) {
        const unsigned old = atomicAdd(&g_ctr[group], 1u);
        s_last = ((old & 1u) == 1u) ? 1 : 0;
    }
    __syncthreads();

    if (s_last) {
        __threadfence();   // see the other chunk's scratch writes
        const float* p0 = &g_part[((unsigned)group) * (T_ * 32)];
        const float* p1 = &g_part[((unsigned)NGROUP + (unsigned)group) * (T_ * 32)];
#pragma unroll
        for (int o = 0; o < 2; ++o) {
            const int oi = tid + o * 256;
            const int t  = oi >> 5;
            const int cc = oi & 31;
            vpool[(unsigned)t * (B_ * C_) + (unsigned)b * C_
                  + (unsigned)(cblk * 32 + cc)]
                = (p0[oi] + p1[oi]) * (1.0f / (float)N_);
        }
    }
}

extern "C" void kernel_launch(void* const* d_in, const int* in_sizes, int n_in,
                              void* d_out, int out_size) {
    const float* x     = (const float*)d_in[0];
    const float* decay = (const float*)d_in[1];
    float* out = (float*)d_out;

    dim3 block(32, NLANES);             // 256 threads
    dim3 grid(C_ / 32, B_, NH);         // 16 x 32 x 2 = 1024 blocks
    lif_dual_kernel<<<grid, block>>>(x, decay, out);
}

// round 6
// speedup vs baseline: 1.8688x; 1.0283x over previous
#include <cuda_runtime.h>

// TritonDualLIF: x [T=16,B=32,N=196,C=512] f32, decay scalar.
// v = d*v + x[t]; vpool[t,b,c] = mean_n(pre-reset v); s = (v>=1); v = s?0:v.
// out = spikes [T,B,N,C] ++ vpool [T,B,C].
//
// float2 lanes, N split into 4 chunks of 49; grid 1024 CTAs (same shape as
// the 74.5us winner) but half the memory instructions. Last-arriving CTA of
// each 4-chunk group combines partials and writes vpool.

#define T_ 16
#define B_ 32
#define N_ 196
#define C_ 512
#define C2 (C_ / 2)        // 256 float2 per row
#define NH 4
#define NSUB 49
#define NLANES 8
#define JMAX 7             // ty==0 -> 7 iters (rows 0..48 step 8 + row 48), else 6
#define NGROUP 256         // B_ * (C2/32) = 32 * 8

// Per-chunk partial sums: [NH][group][T*32] float2 = 4 MB.
__device__ float2   g_part[NH * NGROUP * T_ * 32];
__device__ unsigned g_ctr[NGROUP];   // parity mod 4 elects the combiner

__global__ __launch_bounds__(256, 4)
void lif_dual_kernel(const float2* __restrict__ x,
                     const float* __restrict__ decay,
                     float* __restrict__ out) {
    const int tx   = threadIdx.x;     // c2 lane 0..31
    const int ty   = threadIdx.y;     // n lane 0..7
    const int cblk = blockIdx.x;      // 0..7
    const int b    = blockIdx.y;      // 0..31
    const int z    = blockIdx.z;      // 0..3  (N chunk)
    const float d  = decay[0];

    float2* __restrict__ spikes = (float2*)out;
    float2* __restrict__ vpool  = (float2*)(out + (size_t)T_ * B_ * N_ * C_);

    __shared__ float2 red[NLANES][T_][32];  // exclusive slots, no in-loop sync
    __shared__ int    s_last;

    float2 v[JMAX];
#pragma unroll
    for (int j = 0; j < JMAX; ++j) v[j] = make_float2(0.f, 0.f);

    const unsigned c2      = (unsigned)cblk * 32u + (unsigned)tx;
    const unsigned bbase   = (unsigned)b * (N_ * C2)
                           + (unsigned)(z * NSUB + ty) * C2 + c2;
    const unsigned tstride = (unsigned)(B_ * N_ * C2);
    const int jcnt = (ty == 0) ? JMAX : (JMAX - 1);

    for (int t = 0; t < T_; ++t) {
        const unsigned tb = (unsigned)t * tstride + bbase;
        float2 part = make_float2(0.f, 0.f);
#pragma unroll
        for (int j = 0; j < JMAX; ++j) {
            if (j < jcnt) {
                const unsigned idx = tb + (unsigned)(j * (NLANES * C2));
                const float2 xv = x[idx];
                float2 vv;
                vv.x = fmaf(d, v[j].x, xv.x);
                vv.y = fmaf(d, v[j].y, xv.y);
                part.x += vv.x;                   // pre-reset membrane
                part.y += vv.y;
                float2 s;
                const bool fx = (vv.x >= 1.0f);
                const bool fy = (vv.y >= 1.0f);
                s.x = fx ? 1.0f : 0.0f;
                s.y = fy ? 1.0f : 0.0f;
                spikes[idx] = s;
                v[j].x = fx ? 0.0f : vv.x;        // hard reset
                v[j].y = fy ? 0.0f : vv.y;
            }
        }
        red[ty][t][tx] = part;                    // exclusive slot
    }

    __syncthreads();

    // Reduce 8 lanes -> chunk partial [T_*32] float2, store to scratch.
    const int tid   = ty * 32 + tx;
    const int group = b * 8 + cblk;               // 0..255
    float2* gp = &g_part[((unsigned)z * NGROUP + (unsigned)group) * (T_ * 32)];
#pragma unroll
    for (int o = 0; o < 2; ++o) {
        const int oi = tid + o * 256;             // 0..511
        const int t  = oi >> 5;
        const int cc = oi & 31;
        float2 sum = red[0][t][cc];
#pragma unroll
        for (int k = 1; k < NLANES; ++k) {
            sum.x += red[k][t][cc].x;
            sum.y += red[k][t][cc].y;
        }
        gp[oi] = sum;
    }

    __threadfence();
    __syncthreads();
    if (tid == 0) {
        const unsigned old = atomicAdd(&g_ctr[group], 1u);
        s_last = ((old & 3u) == 3u) ? 1 : 0;
    }
    __syncthreads();

    if (s_last) {
        __threadfence();   // acquire: see all chunks' scratch writes
        const float2* p0 = &g_part[((unsigned)group) * (T_ * 32)];
        const float2* p1 = &g_part[((unsigned)(NGROUP + group)) * (T_ * 32)];
        const float2* p2 = &g_part[((unsigned)(2 * NGROUP + group)) * (T_ * 32)];
        const float2* p3 = &g_part[((unsigned)(3 * NGROUP + group)) * (T_ * 32)];
#pragma unroll
        for (int o = 0; o < 2; ++o) {
            const int oi = tid + o * 256;
            const int t  = oi >> 5;
            const int cc = oi & 31;
            float2 r;
            r.x = ((p0[oi].x + p1[oi].x) + (p2[oi].x + p3[oi].x)) * (1.0f / (float)N_);
            r.y = ((p0[oi].y + p1[oi].y) + (p2[oi].y + p3[oi].y)) * (1.0f / (float)N_);
            vpool[(unsigned)t * (B_ * C2) + (unsigned)b * C2
                  + (unsigned)cblk * 32u + (unsigned)cc] = r;
        }
    }
}

extern "C" void kernel_launch(void* const* d_in, const int* in_sizes, int n_in,
                              void* d_out, int out_size) {
    const float2* x    = (const float2*)d_in[0];
    const float* decay = (const float*)d_in[1];
    float* out = (float*)d_out;

    dim3 block(32, NLANES);             // 256 threads
    dim3 grid(C2 / 32, B_, NH);         // 8 x 32 x 4 = 1024 blocks
    lif_dual_kernel<<<grid, block>>>(x, decay, out);
}